// round 13
// baseline (speedup 1.0000x reference)
#include <cuda_runtime.h>
#include <cuda_bf16.h>
#include <cstdint>

// x: (128,256,512) f32, weight: (256,512,512) f32, out: (128,256,512) f32
// out[b,r,s] = log( sum_n exp(x)*exp(w) ) - log( sum_n exp(w) )
// CTA: 128 batch rows x 128 s-cols, one region. 8 producer + 8 consumer warps.
// Pipeline: KC=64 chunks x 8, 4 smem B buffers (producers up to 3 ahead).
#define B_  128
#define R_  256
#define N_  512
#define S_  512
#define TS  128
#define KC  64
#define NCH 8
#define NBUF 4
#define THREADS 512
#define AK  520      // A row stride (bf16): rows shift 4 banks -> LDSM conflict-free
#define BKC 72       // B row stride (bf16): 144B -> +4 banks per row -> conflict-free

#define OFF_RSUM 128
#define OFF_A    768
#define OFF_B    (OFF_A + B_ * AK * 2)
#define B_BUF_BYTES (TS * BKC * 2)
#define SMEM_BYTES (OFF_B + NBUF * B_BUF_BYTES)

__device__ __forceinline__ void mma16816(float c[4], const uint32_t a[4], uint32_t b0, uint32_t b1) {
    asm volatile(
        "mma.sync.aligned.m16n8k16.row.col.f32.bf16.bf16.f32 "
        "{%0,%1,%2,%3}, {%4,%5,%6,%7}, {%8,%9}, {%0,%1,%2,%3};\n"
        : "+f"(c[0]), "+f"(c[1]), "+f"(c[2]), "+f"(c[3])
        : "r"(a[0]), "r"(a[1]), "r"(a[2]), "r"(a[3]), "r"(b0), "r"(b1));
}
__device__ __forceinline__ void ldsm4(uint32_t f[4], uint32_t addr) {
    asm volatile("ldmatrix.sync.aligned.m8n8.x4.shared.b16 {%0,%1,%2,%3}, [%4];"
                 : "=r"(f[0]), "=r"(f[1]), "=r"(f[2]), "=r"(f[3]) : "r"(addr));
}
__device__ __forceinline__ uint32_t smem_u32(const void* p) {
    uint32_t a;
    asm("{ .reg .u64 t; cvta.to.shared.u64 t, %1; cvt.u32.u64 %0, t; }" : "=r"(a) : "l"(p));
    return a;
}
__device__ __forceinline__ void mbar_init(uint32_t a, uint32_t cnt) {
    asm volatile("mbarrier.init.shared.b64 [%0], %1;" :: "r"(a), "r"(cnt) : "memory");
}
__device__ __forceinline__ void mbar_arrive(uint32_t a) {
    asm volatile("mbarrier.arrive.shared.b64 _, [%0];" :: "r"(a) : "memory");
}
// Suspended try_wait with timeout hint (pattern from known-good production kernels).
__device__ __forceinline__ void mbar_wait(uint32_t a, uint32_t parity) {
    asm volatile(
        "{\n\t.reg .pred P1;\n\t"
        "WL%=:\n\t"
        "mbarrier.try_wait.parity.shared::cta.b64 P1, [%0], %1, 0x989680;\n\t"
        "@P1 bra WD%=;\n\t"
        "bra.uni WL%=;\n\t"
        "WD%=:\n\t}"
        :: "r"(a), "r"(parity) : "memory");
}
__device__ __forceinline__ uint2 exp4_bf16(float4 v) {
    __nv_bfloat162 h01 = __floats2bfloat162_rn(__expf(v.x), __expf(v.y));
    __nv_bfloat162 h23 = __floats2bfloat162_rn(__expf(v.z), __expf(v.w));
    return make_uint2(*reinterpret_cast<uint32_t*>(&h01), *reinterpret_cast<uint32_t*>(&h23));
}
__device__ __forceinline__ float sum4_of(uint2 u) {
    float2 f01 = __bfloat1622float2(*reinterpret_cast<__nv_bfloat162*>(&u.x));
    float2 f23 = __bfloat1622float2(*reinterpret_cast<__nv_bfloat162*>(&u.y));
    return f01.x + f01.y + f23.x + f23.y;
}

__global__ __launch_bounds__(THREADS, 1)
void sumlayer_kernel(const float* __restrict__ x,
                     const float* __restrict__ w,
                     float* __restrict__ out) {
    extern __shared__ unsigned char smem_raw[];
    const uint32_t base = smem_u32(smem_raw);
    float*         rsum = reinterpret_cast<float*>(smem_raw + OFF_RSUM);   // [128] log(sum exp(w))
    __nv_bfloat16* A    = reinterpret_cast<__nv_bfloat16*>(smem_raw + OFF_A);

    // mbarriers: full[0..3] at base+0..31, empt[0..3] at base+32..63, rsum at +64, A at +72
    const uint32_t mbarR = base + 64, mbarA = base + 72;

    const int r    = blockIdx.y;
    const int s0   = blockIdx.x * TS;
    const int tid  = threadIdx.x;
    const int warp = tid >> 5;
    const int lane = tid & 31;

    if (tid == 0) {
        #pragma unroll
        for (int i = 0; i < NBUF; ++i) {
            mbar_init(base + 8 * i, 8);        // full[i]: 8 producer warps
            mbar_init(base + 32 + 8 * i, 8);   // empt[i]: 8 consumer warps
        }
        mbar_init(mbarR, 8);
        mbar_init(mbarA, THREADS);             // every thread arrives once
    }
    __syncthreads();

    // ---- Phase A (ALL 16 warps, 8 rows each): A[b][n] = bf16(exp(x[b,r,n])) ----
    {
        #pragma unroll 1
        for (int tt = 0; tt < 2; ++tt) {
            float4 v[4][4];
            #pragma unroll
            for (int t = 0; t < 4; ++t) {
                const int b = warp * 8 + tt * 4 + t;
                const float4* xr = reinterpret_cast<const float4*>(x + ((size_t)b * R_ + r) * N_);
                #pragma unroll
                for (int j = 0; j < 4; ++j) v[t][j] = xr[lane + j * 32];
            }
            #pragma unroll
            for (int t = 0; t < 4; ++t) {
                const int b = warp * 8 + tt * 4 + t;
                #pragma unroll
                for (int j = 0; j < 4; ++j)
                    *reinterpret_cast<uint2*>(A + b * AK + (lane + j * 32) * 4) = exp4_bf16(v[t][j]);
            }
        }
        mbar_arrive(mbarA);
    }

    if (warp < 8) {
        // =================== PRODUCERS (warps 0-7): weight chunks ===================
        // Warp p owns s-rows p*16 .. p*16+15. Per chunk: 16 rows x 64 cols.
        const int p   = warp;
        const int sub = lane >> 4;
        const int c16 = lane & 15;
        float rp[16];
        #pragma unroll
        for (int t = 0; t < 16; ++t) rp[t] = 0.f;

        #pragma unroll 1
        for (int kc = 0; kc < NCH; ++kc) {
            const int buf = kc & 3;
            if (kc >= NBUF) mbar_wait(base + 32 + 8 * buf, 0);   // consumer freed it (once)
            __nv_bfloat16* Bb = reinterpret_cast<__nv_bfloat16*>(
                smem_raw + OFF_B + buf * B_BUF_BYTES);

            float4 pv[8];
            #pragma unroll
            for (int t = 0; t < 8; ++t) {
                const int row = p * 16 + 2 * t + sub;
                pv[t] = *reinterpret_cast<const float4*>(
                    w + ((size_t)r * S_ + (s0 + row)) * N_ + kc * KC + c16 * 4);
            }
            #pragma unroll
            for (int t = 0; t < 8; ++t) {
                const int row = p * 16 + 2 * t + sub;
                uint2 u = exp4_bf16(pv[t]);
                *reinterpret_cast<uint2*>(Bb + row * BKC + c16 * 4) = u;
                rp[2 * t + sub] += sum4_of(u);
            }
            __syncwarp();
            if (lane == 0) mbar_arrive(base + 8 * buf);          // full[buf]
        }

        // ---- rsum: the 16 lanes of one sub-half share a row ----
        #pragma unroll
        for (int t = 0; t < 8; ++t) {
            const int t2 = 2 * t + sub;
            float s = rp[t2];
            #pragma unroll
            for (int o = 8; o; o >>= 1) s += __shfl_xor_sync(0xffffffffu, s, o);
            if (c16 == 0) rsum[p * 16 + t2] = __logf(s);
        }
        __syncwarp();
        if (lane == 0) mbar_arrive(mbarR);

    } else {
        // =================== CONSUMERS (warps 8-15): LDSM + MMA ===================
        const int cw = warp - 8;
        const int wm = cw & 3;     // 32-row m-block
        const int wn = cw >> 2;    // 64-col n-block
        const int g  = lane >> 2;
        const int i4 = lane & 3;

        float acc[2][8][4];
        #pragma unroll
        for (int mt = 0; mt < 2; ++mt)
            #pragma unroll
            for (int nt = 0; nt < 8; ++nt)
                #pragma unroll
                for (int q = 0; q < 4; ++q) acc[mt][nt][q] = 0.f;

        const uint32_t aoff = base + OFF_A +
            2u * ((wm * 32 + (lane & 7) + ((lane >> 3) & 1) * 8) * AK + (lane >> 4) * 8);
        const uint32_t boff = base + OFF_B +
            2u * ((wn * 64 + (lane & 7) + (lane >> 4) * 8) * BKC + ((lane >> 3) & 1) * 8);

        mbar_wait(mbarA, 0);   // A tile complete

        #pragma unroll 1
        for (int kc = 0; kc < NCH; ++kc) {
            const int buf = kc & 3;
            mbar_wait(base + 8 * buf, (kc >> 2) & 1);            // full[buf]
            const uint32_t Bcu = boff + (uint32_t)(buf * B_BUF_BYTES);
            #pragma unroll
            for (int ks = 0; ks < 4; ++ks) {
                const uint32_t ak = aoff + 2u * (kc * KC + ks * 16);
                uint32_t a0[4], a1[4], b[4][4];
                ldsm4(a0, ak);
                ldsm4(a1, ak + 2u * 16 * AK);
                #pragma unroll
                for (int nb = 0; nb < 4; ++nb)
                    ldsm4(b[nb], Bcu + 2u * (nb * 16 * BKC + ks * 16));
                #pragma unroll
                for (int nb = 0; nb < 4; ++nb) {
                    mma16816(acc[0][nb * 2],     a0, b[nb][0], b[nb][1]);
                    mma16816(acc[1][nb * 2],     a1, b[nb][0], b[nb][1]);
                    mma16816(acc[0][nb * 2 + 1], a0, b[nb][2], b[nb][3]);
                    mma16816(acc[1][nb * 2 + 1], a1, b[nb][2], b[nb][3]);
                }
            }
            __syncwarp();
            if (lane == 0) mbar_arrive(base + 32 + 8 * buf);     // empt[buf]
        }

        // ---- Epilogue: out = log(acc) - rsum[s] ----
        mbar_wait(mbarR, 0);
        #pragma unroll
        for (int mt = 0; mt < 2; ++mt) {
            const int row = wm * 32 + mt * 16 + g;
            const size_t ob0 = ((size_t)row       * R_ + r) * S_ + s0;
            const size_t ob1 = ((size_t)(row + 8) * R_ + r) * S_ + s0;
            #pragma unroll
            for (int nt = 0; nt < 8; ++nt) {
                const int cloc = wn * 64 + nt * 8 + 2 * i4;
                const float l0 = rsum[cloc];
                const float l1 = rsum[cloc + 1];
                float2 o0 = make_float2(__logf(acc[mt][nt][0]) - l0,
                                        __logf(acc[mt][nt][1]) - l1);
                float2 o1 = make_float2(__logf(acc[mt][nt][2]) - l0,
                                        __logf(acc[mt][nt][3]) - l1);
                *reinterpret_cast<float2*>(out + ob0 + cloc) = o0;
                *reinterpret_cast<float2*>(out + ob1 + cloc) = o1;
            }
        }
    }
}

extern "C" void kernel_launch(void* const* d_in, const int* in_sizes, int n_in,
                              void* d_out, int out_size) {
    const float* x = reinterpret_cast<const float*>(d_in[0]);
    const float* w = reinterpret_cast<const float*>(d_in[1]);
    if (n_in >= 2 && in_sizes[0] != B_ * R_ * N_) {
        x = reinterpret_cast<const float*>(d_in[1]);
        w = reinterpret_cast<const float*>(d_in[0]);
    }
    float* out = reinterpret_cast<float*>(d_out);

    (void)cudaFuncSetAttribute(sumlayer_kernel, cudaFuncAttributeMaxDynamicSharedMemorySize, SMEM_BYTES);

    dim3 grid(S_ / TS, R_);   // s-blocks fastest: same-region CTAs share x via L2
    sumlayer_kernel<<<grid, THREADS, SMEM_BYTES>>>(x, w, out);
}

// round 14
// speedup vs baseline: 1.2273x; 1.2273x over previous
#include <cuda_runtime.h>
#include <cuda_bf16.h>
#include <cstdint>

// x: (128,256,512) f32, weight: (256,512,512) f32, out: (128,256,512) f32
// out[b,r,s] = log( sum_n exp(x)*exp(w) ) - log( sum_n exp(w) )
// CTA: 128 x 128 tile, one region. 8 producer + 8 consumer warps, KC=128 x 4 chunks,
// 2 bf16 B buffers. Producer is register-double-buffered at half-chunk granularity so
// 8 LDG.128 per warp stay in flight continuously (MLP -> HBM bandwidth).
#define B_  128
#define R_  256
#define N_  512
#define S_  512
#define TS  128
#define KC  128
#define NCH 4
#define THREADS 512
#define AK  520      // A row stride (bf16): rows shift 4 banks -> LDSM conflict-free
#define BK  136      // B row stride (bf16): same property

#define OFF_RSUM 128
#define OFF_A    768
#define OFF_B    (OFF_A + B_ * AK * 2)
#define B_BUF_BYTES (TS * BK * 2)
#define SMEM_BYTES (OFF_B + 2 * B_BUF_BYTES)

__device__ __forceinline__ void mma16816(float c[4], const uint32_t a[4], uint32_t b0, uint32_t b1) {
    asm volatile(
        "mma.sync.aligned.m16n8k16.row.col.f32.bf16.bf16.f32 "
        "{%0,%1,%2,%3}, {%4,%5,%6,%7}, {%8,%9}, {%0,%1,%2,%3};\n"
        : "+f"(c[0]), "+f"(c[1]), "+f"(c[2]), "+f"(c[3])
        : "r"(a[0]), "r"(a[1]), "r"(a[2]), "r"(a[3]), "r"(b0), "r"(b1));
}
__device__ __forceinline__ void ldsm4(uint32_t f[4], uint32_t addr) {
    asm volatile("ldmatrix.sync.aligned.m8n8.x4.shared.b16 {%0,%1,%2,%3}, [%4];"
                 : "=r"(f[0]), "=r"(f[1]), "=r"(f[2]), "=r"(f[3]) : "r"(addr));
}
__device__ __forceinline__ uint32_t smem_u32(const void* p) {
    uint32_t a;
    asm("{ .reg .u64 t; cvta.to.shared.u64 t, %1; cvt.u32.u64 %0, t; }" : "=r"(a) : "l"(p));
    return a;
}
__device__ __forceinline__ void mbar_init(uint32_t a, uint32_t cnt) {
    asm volatile("mbarrier.init.shared.b64 [%0], %1;" :: "r"(a), "r"(cnt) : "memory");
}
__device__ __forceinline__ void mbar_arrive(uint32_t a) {
    asm volatile("mbarrier.arrive.shared.b64 _, [%0];" :: "r"(a) : "memory");
}
__device__ __forceinline__ void mbar_wait(uint32_t a, uint32_t parity) {
    asm volatile(
        "{\n\t.reg .pred P;\n\t"
        "W%=:\n\t"
        "mbarrier.try_wait.parity.shared.b64 P, [%0], %1;\n\t"
        "@!P bra W%=;\n\t}"
        :: "r"(a), "r"(parity) : "memory");
}
__device__ __forceinline__ uint2 exp4_bf16(float4 v) {
    __nv_bfloat162 h01 = __floats2bfloat162_rn(__expf(v.x), __expf(v.y));
    __nv_bfloat162 h23 = __floats2bfloat162_rn(__expf(v.z), __expf(v.w));
    return make_uint2(*reinterpret_cast<uint32_t*>(&h01), *reinterpret_cast<uint32_t*>(&h23));
}
__device__ __forceinline__ float sum4_of(uint2 u) {
    float2 f01 = __bfloat1622float2(*reinterpret_cast<__nv_bfloat162*>(&u.x));
    float2 f23 = __bfloat1622float2(*reinterpret_cast<__nv_bfloat162*>(&u.y));
    return f01.x + f01.y + f23.x + f23.y;
}

__global__ __launch_bounds__(THREADS, 1)
void sumlayer_kernel(const float* __restrict__ x,
                     const float* __restrict__ w,
                     float* __restrict__ out) {
    extern __shared__ unsigned char smem_raw[];
    const uint32_t base = smem_u32(smem_raw);
    float*         rsum = reinterpret_cast<float*>(smem_raw + OFF_RSUM);   // [128] log(sum exp(w))
    __nv_bfloat16* A    = reinterpret_cast<__nv_bfloat16*>(smem_raw + OFF_A);
    __nv_bfloat16* Bs   = reinterpret_cast<__nv_bfloat16*>(smem_raw + OFF_B);
    const uint32_t full0 = base,      full1 = base + 8;
    const uint32_t empt0 = base + 16, empt1 = base + 24;
    const uint32_t mbarR = base + 32, mbarA = base + 40;

    const int r    = blockIdx.y;
    const int s0   = blockIdx.x * TS;
    const int tid  = threadIdx.x;
    const int warp = tid >> 5;
    const int lane = tid & 31;

    if (tid == 0) {
        mbar_init(full0, 8); mbar_init(full1, 8);   // 8 producer warps (lane 0)
        mbar_init(empt0, 8); mbar_init(empt1, 8);   // 8 consumer warps (lane 0)
        mbar_init(mbarR, 8);
        mbar_init(mbarA, THREADS);                  // every thread arrives once
    }
    __syncthreads();

    // ---- Phase A (ALL 16 warps, 8 rows each): A[b][n] = bf16(exp(x[b,r,n])) ----
    {
        #pragma unroll 1
        for (int tt = 0; tt < 2; ++tt) {
            float4 v[4][4];
            #pragma unroll
            for (int t = 0; t < 4; ++t) {
                const int b = warp * 8 + tt * 4 + t;
                const float4* xr = reinterpret_cast<const float4*>(x + ((size_t)b * R_ + r) * N_);
                #pragma unroll
                for (int j = 0; j < 4; ++j) v[t][j] = xr[lane + j * 32];
            }
            #pragma unroll
            for (int t = 0; t < 4; ++t) {
                const int b = warp * 8 + tt * 4 + t;
                #pragma unroll
                for (int j = 0; j < 4; ++j)
                    *reinterpret_cast<uint2*>(A + b * AK + (lane + j * 32) * 4) = exp4_bf16(v[t][j]);
            }
        }
        mbar_arrive(mbarA);
    }

    if (warp < 8) {
        // =================== PRODUCERS (warps 0-7) ===================
        // Warp p owns s-rows p*16..p*16+15. Half-chunk h (= kc*2 + half): 8 rows x 128 cols.
        // Register double buffer: loads for h+1 are issued BEFORE processing h, so 8
        // LDG.128 per warp are continuously in flight.
        const int p = warp;
        const float4* wbase = reinterpret_cast<const float4*>(w) +
                              ((size_t)r * S_ + s0) * (N_ / 4);
        float rp[16];
        #pragma unroll
        for (int t = 0; t < 16; ++t) rp[t] = 0.f;

        float4 pv[8], pv2[8];
        // preload h=0 (kc=0, half=0): rows p*16 + 0..7
        #pragma unroll
        for (int t = 0; t < 8; ++t)
            pv[t] = wbase[(size_t)(p * 16 + t) * (N_ / 4) + 0 * 32 + lane];

        #pragma unroll 1
        for (int h = 0; h < 8; ++h) {
            const int kc   = h >> 1;
            const int half = h & 1;

            // 1) issue next half-chunk's loads (registers -> no buffer dependency)
            if (h < 7) {
                const int hn = h + 1;
                const int kcn = hn >> 1, halfn = hn & 1;
                #pragma unroll
                for (int t = 0; t < 8; ++t)
                    pv2[t] = wbase[(size_t)(p * 16 + halfn * 8 + t) * (N_ / 4) + kcn * 32 + lane];
            }

            // 2) buffer-free wait (first half of a chunk only), overlapped by the loads above
            if (half == 0 && kc >= 2) mbar_wait(kc & 1 ? empt1 : empt0, 0);

            // 3) process current half-chunk: exp + STS + rsum partial
            __nv_bfloat16* Bb = Bs + (kc & 1) * (TS * BK);
            #pragma unroll
            for (int t = 0; t < 8; ++t) {
                const int row = p * 16 + half * 8 + t;
                uint2 u = exp4_bf16(pv[t]);
                *reinterpret_cast<uint2*>(Bb + row * BK + lane * 4) = u;
                rp[half * 8 + t] += sum4_of(u);
            }
            if (half == 1) {
                __syncwarp();
                if (lane == 0) mbar_arrive(kc & 1 ? full1 : full0);
            }
            #pragma unroll
            for (int t = 0; t < 8; ++t) pv[t] = pv2[t];
        }

        // ---- rsum: one 32-lane reduction per owned row ----
        #pragma unroll
        for (int t = 0; t < 16; ++t) {
            float s = rp[t];
            #pragma unroll
            for (int o = 16; o; o >>= 1) s += __shfl_xor_sync(0xffffffffu, s, o);
            if (lane == 0) rsum[p * 16 + t] = __logf(s);
        }
        __syncwarp();
        if (lane == 0) mbar_arrive(mbarR);

    } else {
        // =================== CONSUMERS (warps 8-15): LDSM + MMA ===================
        const int cw = warp - 8;
        const int wm = cw & 3;     // 32-row m-block
        const int wn = cw >> 2;    // 64-col n-block
        const int g  = lane >> 2;
        const int i4 = lane & 3;

        float acc[2][8][4];
        #pragma unroll
        for (int mt = 0; mt < 2; ++mt)
            #pragma unroll
            for (int nt = 0; nt < 8; ++nt)
                #pragma unroll
                for (int q = 0; q < 4; ++q) acc[mt][nt][q] = 0.f;

        const uint32_t aoff = base + OFF_A +
            2u * ((wm * 32 + (lane & 7) + ((lane >> 3) & 1) * 8) * AK + (lane >> 4) * 8);
        const uint32_t boff = base + OFF_B +
            2u * ((wn * 64 + (lane & 7) + (lane >> 4) * 8) * BK + ((lane >> 3) & 1) * 8);

        mbar_wait(mbarA, 0);   // A tile complete

        #pragma unroll 1
        for (int kc = 0; kc < NCH; ++kc) {
            mbar_wait(kc & 1 ? full1 : full0, (kc >> 1) & 1);
            const uint32_t Bcu = boff + (uint32_t)((kc & 1) * B_BUF_BYTES);
            #pragma unroll
            for (int ks = 0; ks < 8; ++ks) {
                const uint32_t ak = aoff + 2u * (kc * KC + ks * 16);
                uint32_t a0[4], a1[4], b[4][4];
                ldsm4(a0, ak);
                ldsm4(a1, ak + 2u * 16 * AK);
                #pragma unroll
                for (int nb = 0; nb < 4; ++nb)
                    ldsm4(b[nb], Bcu + 2u * (nb * 16 * BK + ks * 16));
                #pragma unroll
                for (int nb = 0; nb < 4; ++nb) {
                    mma16816(acc[0][nb * 2],     a0, b[nb][0], b[nb][1]);
                    mma16816(acc[1][nb * 2],     a1, b[nb][0], b[nb][1]);
                    mma16816(acc[0][nb * 2 + 1], a0, b[nb][2], b[nb][3]);
                    mma16816(acc[1][nb * 2 + 1], a1, b[nb][2], b[nb][3]);
                }
            }
            __syncwarp();
            if (lane == 0) mbar_arrive(kc & 1 ? empt1 : empt0);
        }

        // ---- Epilogue: out = log(acc) - rsum[s] ----
        mbar_wait(mbarR, 0);
        #pragma unroll
        for (int mt = 0; mt < 2; ++mt) {
            const int row = wm * 32 + mt * 16 + g;
            const size_t ob0 = ((size_t)row       * R_ + r) * S_ + s0;
            const size_t ob1 = ((size_t)(row + 8) * R_ + r) * S_ + s0;
            #pragma unroll
            for (int nt = 0; nt < 8; ++nt) {
                const int cloc = wn * 64 + nt * 8 + 2 * i4;
                const float l0 = rsum[cloc];
                const float l1 = rsum[cloc + 1];
                float2 o0 = make_float2(__logf(acc[mt][nt][0]) - l0,
                                        __logf(acc[mt][nt][1]) - l1);
                float2 o1 = make_float2(__logf(acc[mt][nt][2]) - l0,
                                        __logf(acc[mt][nt][3]) - l1);
                *reinterpret_cast<float2*>(out + ob0 + cloc) = o0;
                *reinterpret_cast<float2*>(out + ob1 + cloc) = o1;
            }
        }
    }
}

extern "C" void kernel_launch(void* const* d_in, const int* in_sizes, int n_in,
                              void* d_out, int out_size) {
    const float* x = reinterpret_cast<const float*>(d_in[0]);
    const float* w = reinterpret_cast<const float*>(d_in[1]);
    if (n_in >= 2 && in_sizes[0] != B_ * R_ * N_) {
        x = reinterpret_cast<const float*>(d_in[1]);
        w = reinterpret_cast<const float*>(d_in[0]);
    }
    float* out = reinterpret_cast<float*>(d_out);

    (void)cudaFuncSetAttribute(sumlayer_kernel, cudaFuncAttributeMaxDynamicSharedMemorySize, SMEM_BYTES);

    dim3 grid(S_ / TS, R_);   // s-blocks fastest: same-region CTAs share x via L2
    sumlayer_kernel<<<grid, THREADS, SMEM_BYTES>>>(x, w, out);
}